// round 7
// baseline (speedup 1.0000x reference)
#include <cuda_runtime.h>
#include <cuda_bf16.h>
#include <cstdint>
#include <cstddef>

// ---------------------------------------------------------------------------
// Problem constants
// ---------------------------------------------------------------------------
#define B_  256
#define T_  100
#define I_  1024
#define H_  2048
#define O_  10
#define M1  (B_ * T_)   // 25600

// GEMM tiling: 64x64 CTA tile, warp 16x32, 8 warps
#define BM 64
#define BN 64
#define BK 32
#define STRIDE 40                    // padded bf16 row stride in smem (80B rows)
#define NSTAGE 4
#define SLOT   (BM * STRIDE)         // 2560 elems per array per stage
#define ABYTES (NSTAGE * SLOT * 2)   // 20480 bytes per operand array
#define SMEM_BYTES (4 * ABYTES)      // 81920 bytes

#define NBLK_STEP 128                // persistent grid size (1 CTA/SM wave)

// ---------------------------------------------------------------------------
// Device scratch
// ---------------------------------------------------------------------------
__device__ float g_hall[(size_t)T_ * B_ * H_];         // [t][b][h]
__device__ __nv_bfloat16 g_xhi[(size_t)M1 * I_];       // [t][b][i]  (reordered!)
__device__ __nv_bfloat16 g_xlo[(size_t)M1 * I_];
__device__ __nv_bfloat16 g_WinT_hi[(size_t)H_ * I_];   // [h][i]
__device__ __nv_bfloat16 g_WinT_lo[(size_t)H_ * I_];
__device__ __nv_bfloat16 g_WT_hi[(size_t)H_ * H_];     // [n][k]
__device__ __nv_bfloat16 g_WT_lo[(size_t)H_ * H_];
__device__ __nv_bfloat16 g_hA_hi[(size_t)B_ * H_], g_hA_lo[(size_t)B_ * H_];
__device__ __nv_bfloat16 g_hB_hi[(size_t)B_ * H_], g_hB_lo[(size_t)B_ * H_];
__device__ unsigned g_bar_count = 0;
__device__ unsigned g_bar_sense = 0;

// ---------------------------------------------------------------------------
// Helpers
// ---------------------------------------------------------------------------
__device__ __forceinline__ uint32_t s2u(const void* p) {
    uint32_t a;
    asm("{ .reg .u64 t; cvta.to.shared.u64 t, %1; cvt.u32.u64 %0, t; }" : "=r"(a) : "l"(p));
    return a;
}
__device__ __forceinline__ void cp16(uint32_t s, const void* g) {
    asm volatile("cp.async.cg.shared.global [%0], [%1], 16;" :: "r"(s), "l"(g));
}
#define CP_COMMIT()  asm volatile("cp.async.commit_group;")
#define CP_WAIT(N)   asm volatile("cp.async.wait_group %0;" :: "n"(N))

__device__ __forceinline__ void mma_bf16(float* d, const uint32_t* a, uint32_t b0, uint32_t b1) {
    asm volatile(
        "mma.sync.aligned.m16n8k16.row.col.f32.bf16.bf16.f32 "
        "{%0,%1,%2,%3}, {%4,%5,%6,%7}, {%8,%9}, {%0,%1,%2,%3};"
        : "+f"(d[0]), "+f"(d[1]), "+f"(d[2]), "+f"(d[3])
        : "r"(a[0]), "r"(a[1]), "r"(a[2]), "r"(a[3]), "r"(b0), "r"(b1));
}
__device__ __forceinline__ void ldsm4(uint32_t* r, uint32_t addr) {
    asm volatile("ldmatrix.sync.aligned.m8n8.x4.shared.b16 {%0,%1,%2,%3}, [%4];"
        : "=r"(r[0]), "=r"(r[1]), "=r"(r[2]), "=r"(r[3]) : "r"(addr));
}
__device__ __forceinline__ void split2(float v, __nv_bfloat16& h, __nv_bfloat16& l) {
    h = __float2bfloat16(v);
    l = __float2bfloat16(v - __bfloat162float(h));
}

// bf16x3 compute on one smem stage via ldmatrix (mapping validated in R6).
__device__ __forceinline__ void compute_stage_lm(
    uint32_t sAh, uint32_t sAl, uint32_t sBh, uint32_t sBl,
    uint32_t a_off, uint32_t b_off0, uint32_t b_off1, float (*d)[4])
{
    #pragma unroll
    for (int kh = 0; kh < 2; kh++) {
        const uint32_t ko = kh * 32;   // 16 elems = 32 bytes
        uint32_t ah[4], al[4], bh[4], bl[4];
        ldsm4(ah, sAh + a_off + ko);
        ldsm4(al, sAl + a_off + ko);
        ldsm4(bh, sBh + b_off0 + ko);
        ldsm4(bl, sBl + b_off0 + ko);
        mma_bf16(d[0], ah, bh[0], bh[1]);
        mma_bf16(d[0], ah, bl[0], bl[1]);
        mma_bf16(d[0], al, bh[0], bh[1]);
        mma_bf16(d[1], ah, bh[2], bh[3]);
        mma_bf16(d[1], ah, bl[2], bl[3]);
        mma_bf16(d[1], al, bh[2], bh[3]);
        ldsm4(bh, sBh + b_off1 + ko);
        ldsm4(bl, sBl + b_off1 + ko);
        mma_bf16(d[2], ah, bh[0], bh[1]);
        mma_bf16(d[2], ah, bl[0], bl[1]);
        mma_bf16(d[2], al, bh[0], bh[1]);
        mma_bf16(d[3], ah, bh[2], bh[3]);
        mma_bf16(d[3], ah, bl[2], bl[3]);
        mma_bf16(d[3], al, bh[2], bh[3]);
    }
}
__device__ __forceinline__ uint32_t a_lane_off(int mrow, int lane) {
    return (uint32_t)(((mrow + (lane & 15)) * STRIDE + ((lane >> 4) & 1) * 8) * 2);
}
__device__ __forceinline__ uint32_t b_lane_off(int ncol, int jp, int lane) {
    return (uint32_t)(((ncol + jp * 16 + ((lane >> 4) & 1) * 8 + (lane & 7)) * STRIDE
                       + ((lane >> 3) & 1) * 8) * 2);
}

// ---------------------------------------------------------------------------
// Prologue kernels
// ---------------------------------------------------------------------------
// h0 split (same layout)
__global__ void decomp_kernel(const float* __restrict__ src,
                              __nv_bfloat16* __restrict__ hi,
                              __nv_bfloat16* __restrict__ lo, size_t n4) {
    for (size_t i = (size_t)blockIdx.x * blockDim.x + threadIdx.x; i < n4;
         i += (size_t)gridDim.x * blockDim.x) {
        float4 v = ((const float4*)src)[i];
        __nv_bfloat16 h0, l0, h1, l1, h2, l2, h3, l3;
        split2(v.x, h0, l0); split2(v.y, h1, l1);
        split2(v.z, h2, l2); split2(v.w, h3, l3);
        ((__nv_bfloat162*)hi)[i * 2 + 0] = __halves2bfloat162(h0, h1);
        ((__nv_bfloat162*)hi)[i * 2 + 1] = __halves2bfloat162(h2, h3);
        ((__nv_bfloat162*)lo)[i * 2 + 0] = __halves2bfloat162(l0, l1);
        ((__nv_bfloat162*)lo)[i * 2 + 1] = __halves2bfloat162(l2, l3);
    }
}

// x split + reorder: x[b][t][i] -> g_xhi/g_xlo at [t][b][i]
__global__ void decomp_x_kernel(const float* __restrict__ src) {
    const size_t n4 = (size_t)M1 * I_ / 4;
    constexpr int I4 = I_ / 4;
    for (size_t i = (size_t)blockIdx.x * blockDim.x + threadIdx.x; i < n4;
         i += (size_t)gridDim.x * blockDim.x) {
        const size_t m = i / I4;            // b*T + t
        const int    c = (int)(i - m * I4); // i4 within row
        const int b = (int)(m / T_);
        const int t = (int)(m - (size_t)b * T_);
        float4 v = ((const float4*)src)[i];
        __nv_bfloat16 h0, l0, h1, l1, h2, l2, h3, l3;
        split2(v.x, h0, l0); split2(v.y, h1, l1);
        split2(v.z, h2, l2); split2(v.w, h3, l3);
        const size_t o = ((size_t)t * B_ + b) * I4 + c;
        ((__nv_bfloat162*)g_xhi)[o * 2 + 0] = __halves2bfloat162(h0, h1);
        ((__nv_bfloat162*)g_xhi)[o * 2 + 1] = __halves2bfloat162(h2, h3);
        ((__nv_bfloat162*)g_xlo)[o * 2 + 0] = __halves2bfloat162(l0, l1);
        ((__nv_bfloat162*)g_xlo)[o * 2 + 1] = __halves2bfloat162(l2, l3);
    }
}

__global__ void transpose_decomp_kernel(const float* __restrict__ src, int R, int C,
                                        __nv_bfloat16* __restrict__ dhi,
                                        __nv_bfloat16* __restrict__ dlo) {
    __shared__ float tile[32][33];
    const int bx = blockIdx.x * 32;
    const int by = blockIdx.y * 32;
    const int tx = threadIdx.x, ty = threadIdx.y;
    #pragma unroll
    for (int j = 0; j < 32; j += 8)
        tile[ty + j][tx] = src[(size_t)(by + ty + j) * C + bx + tx];
    __syncthreads();
    #pragma unroll
    for (int j = 0; j < 32; j += 8) {
        float v = tile[tx][ty + j];
        size_t o = (size_t)(bx + ty + j) * R + by + tx;
        __nv_bfloat16 h, l; split2(v, h, l);
        dhi[o] = h; dlo[o] = l;
    }
}

// ---------------------------------------------------------------------------
// Split grid barrier (arrive / wait) — x-part compute overlaps the wait.
// ---------------------------------------------------------------------------
__device__ __forceinline__ void bar_arrive(unsigned target) {
    __threadfence();          // make h stores GPU-visible before arriving
    __syncthreads();
    if (threadIdx.x == 0) {
        unsigned a = atomicAdd(&g_bar_count, 1);
        if (a == NBLK_STEP - 1) {
            atomicExch(&g_bar_count, 0);
            __threadfence();  // order count reset before sense publish
            atomicExch(&g_bar_sense, target);
        }
    }
}
__device__ __forceinline__ void bar_wait(unsigned target) {
    if (threadIdx.x == 0) {
        while (atomicAdd(&g_bar_sense, 0) < target) { __nanosleep(64); }
    }
    __syncthreads();
}

// ---------------------------------------------------------------------------
// Fused persistent kernel: h_t = tanh([x_t, h_{t-1}] @ [Win; W])
// Per step: 32 x-chunks (pre-barrier) + 64 h-chunks (post-barrier), K=3072.
// ---------------------------------------------------------------------------
__global__ void __launch_bounds__(256) step_persistent_kernel() {
    extern __shared__ __nv_bfloat16 sm[];
    const uint32_t sbase = s2u(sm);
    const uint32_t pAh = sbase;
    const uint32_t pAl = sbase + 1 * ABYTES;
    const uint32_t pBh = sbase + 2 * ABYTES;
    const uint32_t pBl = sbase + 3 * ABYTES;

    const int tid = threadIdx.x;
    const int wid = tid >> 5, lane = tid & 31;
    const int mrow = (wid & 3) * 16;
    const int ncol = (wid >> 2) * 32;
    const int bid = blockIdx.x;
    const int rowBase = (bid >> 5) * BM;   // 4 row tiles (B=256)
    const int colBase = (bid & 31) * BN;   // 32 col tiles (H=2048)
    const int lr = tid >> 2, lc = (tid & 3) * 8;
    constexpr int NKX = I_ / BK;   // 32
    constexpr int NKH = H_ / BK;   // 64

    const uint32_t a_off  = a_lane_off(mrow, lane);
    const uint32_t b_off0 = b_lane_off(ncol, 0, lane);
    const uint32_t b_off1 = b_lane_off(ncol, 1, lane);

    __shared__ unsigned s_base;
    if (tid == 0) s_base = atomicAdd(&g_bar_sense, 0u);
    __syncthreads();
    const unsigned base = s_base;

    #pragma unroll 1
    for (int t = 0; t < T_; t++) {
        const __nv_bfloat16* ah  = (t & 1) ? g_hB_hi : g_hA_hi;
        const __nv_bfloat16* al  = (t & 1) ? g_hB_lo : g_hA_lo;
        __nv_bfloat16* whi = (t & 1) ? g_hA_hi : g_hB_hi;
        __nv_bfloat16* wlo = (t & 1) ? g_hA_lo : g_hB_lo;

        const size_t xrow = ((size_t)t * B_ + rowBase + lr) * I_ + lc;

        auto issueX = [&](int slot, int kc) {
            const int k0 = kc * BK;
            const size_t gb = (size_t)(colBase + lr) * I_ + k0 + lc;
            const uint32_t so = (uint32_t)(slot * SLOT + lr * STRIDE + lc) * 2;
            cp16(pAh + so, g_xhi + xrow + k0);
            cp16(pAl + so, g_xlo + xrow + k0);
            cp16(pBh + so, g_WinT_hi + gb);
            cp16(pBl + so, g_WinT_lo + gb);
            CP_COMMIT();
        };
        auto issueH = [&](int slot, int kc) {
            const int k0 = kc * BK;
            const size_t ga = (size_t)(rowBase + lr) * H_ + k0 + lc;
            const size_t gb = (size_t)(colBase + lr) * H_ + k0 + lc;
            const uint32_t so = (uint32_t)(slot * SLOT + lr * STRIDE + lc) * 2;
            cp16(pAh + so, ah + ga);
            cp16(pAl + so, al + ga);
            cp16(pBh + so, g_WT_hi + gb);
            cp16(pBl + so, g_WT_lo + gb);
            CP_COMMIT();
        };

        float d[4][4] = {};

        // ---- Phase 1: x-part (independent of h; overlaps the barrier) ----
        issueX(0, 0); issueX(1, 1); issueX(2, 2);
        #pragma unroll 1
        for (int kc = 0; kc < NKX; kc++) {
            CP_WAIT(2);
            __syncthreads();
            if (kc + 3 < NKX) issueX((kc + 3) & 3, kc + 3);
            const uint32_t so = (uint32_t)((kc & 3) * SLOT) * 2;
            compute_stage_lm(pAh + so, pAl + so, pBh + so, pBl + so,
                             a_off, b_off0, b_off1, d);
        }

        // ---- Barrier: h_{t-1} ready (arrived at end of previous step) ----
        if (t > 0) bar_wait(base + (unsigned)t);

        // ---- Phase 2: h-part ----
        issueH(0, 0); issueH(1, 1); issueH(2, 2);
        #pragma unroll 1
        for (int kc = 0; kc < NKH; kc++) {
            CP_WAIT(2);
            __syncthreads();
            if (kc + 3 < NKH) issueH((kc + 3) & 3, kc + 3);
            const uint32_t so = (uint32_t)((kc & 3) * SLOT) * 2;
            compute_stage_lm(pAh + so, pAl + so, pBh + so, pBl + so,
                             a_off, b_off0, b_off1, d);
        }
        CP_WAIT(0);

        // ---- Epilogue: h = tanh(acc); fp32 + hi/lo split stores ----
        const int g = lane >> 2, tg = lane & 3;
        const int r0 = rowBase + mrow + g;
        const int r1 = r0 + 8;
        #pragma unroll
        for (int j = 0; j < 4; j++) {
            const int col = colBase + ncol + j * 8 + 2 * tg;
            const size_t o0 = ((size_t)t * B_ + r0) * H_ + col;
            const size_t o1 = ((size_t)t * B_ + r1) * H_ + col;
            float h00 = tanhf(d[j][0]);
            float h01 = tanhf(d[j][1]);
            float h10 = tanhf(d[j][2]);
            float h11 = tanhf(d[j][3]);
            *(float2*)&g_hall[o0] = make_float2(h00, h01);
            *(float2*)&g_hall[o1] = make_float2(h10, h11);
            __nv_bfloat16 e0, f0, e1, f1, e2, f2, e3, f3;
            split2(h00, e0, f0); split2(h01, e1, f1);
            split2(h10, e2, f2); split2(h11, e3, f3);
            const size_t w0 = (size_t)r0 * H_ + col;
            const size_t w1 = (size_t)r1 * H_ + col;
            *(__nv_bfloat162*)&whi[w0] = __halves2bfloat162(e0, e1);
            *(__nv_bfloat162*)&wlo[w0] = __halves2bfloat162(f0, f1);
            *(__nv_bfloat162*)&whi[w1] = __halves2bfloat162(e2, e3);
            *(__nv_bfloat162*)&wlo[w1] = __halves2bfloat162(f2, f3);
        }

        if (t < T_ - 1) bar_arrive(base + (unsigned)t + 1u);
    }
}

// ---------------------------------------------------------------------------
// Output head
// ---------------------------------------------------------------------------
__global__ void __launch_bounds__(256) out_kernel(
    const float* __restrict__ lin_w,
    const float* __restrict__ lin_b,
    float* __restrict__ out)
{
    const int bt = blockIdx.x;
    const int t = bt / B_;
    const int b = bt % B_;
    const int tid = threadIdx.x;

    const float* hrow = g_hall + ((size_t)t * B_ + b) * H_;

    float hreg[H_ / 256];
    #pragma unroll
    for (int i = 0; i < H_ / 256; i++)
        hreg[i] = hrow[i * 256 + tid];

    float acc[O_];
    #pragma unroll
    for (int o = 0; o < O_; o++) {
        float s = 0.f;
        #pragma unroll
        for (int i = 0; i < H_ / 256; i++)
            s += hreg[i] * lin_w[(size_t)o * H_ + i * 256 + tid];
        acc[o] = s;
    }

    #pragma unroll
    for (int off = 16; off > 0; off >>= 1)
        #pragma unroll
        for (int o = 0; o < O_; o++)
            acc[o] += __shfl_xor_sync(0xFFFFFFFFu, acc[o], off);

    __shared__ float wsum[8][O_];
    const int lane = tid & 31;
    const int w = tid >> 5;
    if (lane == 0)
        #pragma unroll
        for (int o = 0; o < O_; o++)
            wsum[w][o] = acc[o];
    __syncthreads();

    if (tid < O_) {
        float s = lin_b[tid];
        #pragma unroll
        for (int ww = 0; ww < 8; ww++)
            s += wsum[ww][tid];
        out[((size_t)b * T_ + t) * O_ + tid] = s;
    }
}

// ---------------------------------------------------------------------------
extern "C" void kernel_launch(void* const* d_in, const int* in_sizes, int n_in,
                              void* d_out, int out_size)
{
    const float* x     = (const float*)d_in[0];
    const float* h0    = (const float*)d_in[1];
    const float* Win   = (const float*)d_in[2];
    const float* W     = (const float*)d_in[3];
    const float* lin_w = (const float*)d_in[4];
    const float* lin_b = (const float*)d_in[5];
    float* out = (float*)d_out;

    __nv_bfloat16 *winT_hi, *winT_lo, *wT_hi, *wT_lo, *hA_hi, *hA_lo;
    cudaGetSymbolAddress((void**)&winT_hi, g_WinT_hi);
    cudaGetSymbolAddress((void**)&winT_lo, g_WinT_lo);
    cudaGetSymbolAddress((void**)&wT_hi, g_WT_hi);
    cudaGetSymbolAddress((void**)&wT_lo, g_WT_lo);
    cudaGetSymbolAddress((void**)&hA_hi, g_hA_hi);
    cudaGetSymbolAddress((void**)&hA_lo, g_hA_lo);

    static bool attr_done = false;
    if (!attr_done) {
        cudaFuncSetAttribute(step_persistent_kernel,
                             cudaFuncAttributeMaxDynamicSharedMemorySize, SMEM_BYTES);
        attr_done = true;
    }

    // Prologue
    decomp_x_kernel<<<4096, 256>>>(x);
    decomp_kernel<<<512, 256>>>(h0, hA_hi, hA_lo, (size_t)B_ * H_ / 4);
    transpose_decomp_kernel<<<dim3(H_ / 32, I_ / 32), dim3(32, 8)>>>(Win, I_, H_, winT_hi, winT_lo);
    transpose_decomp_kernel<<<dim3(H_ / 32, H_ / 32), dim3(32, 8)>>>(W, H_, H_, wT_hi, wT_lo);

    // Fused recurrence (xin folded in as K-extension)
    step_persistent_kernel<<<NBLK_STEP, 256, SMEM_BYTES>>>();

    // Output head
    out_kernel<<<T_ * B_, 256>>>(lin_w, lin_b, out);
}

// round 8
// speedup vs baseline: 1.2105x; 1.2105x over previous
#include <cuda_runtime.h>
#include <cuda_bf16.h>
#include <cstdint>
#include <cstddef>

// ---------------------------------------------------------------------------
// Problem constants
// ---------------------------------------------------------------------------
#define B_  256
#define T_  100
#define I_  1024
#define H_  2048
#define O_  10
#define M1  (B_ * T_)   // 25600

// Common tile: 64x64 CTA, 8 warps (4m x 2n), warp 16x32
#define BM 64
#define BN 64

// xin GEMM (R6-proven config): BK=32
#define BKX 32
#define STRX 40
#define SLOTX   (BM * STRX)
#define ABYTESX (4 * SLOTX * 2)        // 4 stages
#define SMEM_X  (4 * ABYTESX)          // 81920 B

// step kernel: BK=64
#define BKS 64
#define STRS 72                        // 144B rows; 144i mod 128 = 16i -> conflict-free
#define SLOTS   (BM * STRS)            // 4608 elems
#define ABYTESS (4 * SLOTS * 2)        // 36864 B per operand array (4 stages)
#define SMEM_S  (4 * ABYTESS)          // 147456 B
#define NBLK_STEP 128

// ---------------------------------------------------------------------------
// Device scratch
// ---------------------------------------------------------------------------
__device__ float g_xin [(size_t)T_ * B_ * H_];         // [t][b][h]
__device__ float g_hall[(size_t)T_ * B_ * H_];         // [t][b][h]
__device__ __nv_bfloat16 g_xhi[(size_t)M1 * I_];
__device__ __nv_bfloat16 g_xlo[(size_t)M1 * I_];
__device__ __nv_bfloat16 g_WinT_hi[(size_t)H_ * I_];   // [h][i]
__device__ __nv_bfloat16 g_WinT_lo[(size_t)H_ * I_];
__device__ __nv_bfloat16 g_WT_hi[(size_t)H_ * H_];     // [n][k]
__device__ __nv_bfloat16 g_WT_lo[(size_t)H_ * H_];
__device__ __nv_bfloat16 g_hA_hi[(size_t)B_ * H_], g_hA_lo[(size_t)B_ * H_];
__device__ __nv_bfloat16 g_hB_hi[(size_t)B_ * H_], g_hB_lo[(size_t)B_ * H_];
__device__ unsigned g_bar_count = 0;
__device__ unsigned g_bar_sense = 0;

// ---------------------------------------------------------------------------
// Helpers
// ---------------------------------------------------------------------------
__device__ __forceinline__ uint32_t s2u(const void* p) {
    uint32_t a;
    asm("{ .reg .u64 t; cvta.to.shared.u64 t, %1; cvt.u32.u64 %0, t; }" : "=r"(a) : "l"(p));
    return a;
}
__device__ __forceinline__ void cp16(uint32_t s, const void* g) {
    asm volatile("cp.async.cg.shared.global [%0], [%1], 16;" :: "r"(s), "l"(g));
}
#define CP_COMMIT()  asm volatile("cp.async.commit_group;")
#define CP_WAIT(N)   asm volatile("cp.async.wait_group %0;" :: "n"(N))

__device__ __forceinline__ void mma_bf16(float* d, const uint32_t* a, uint32_t b0, uint32_t b1) {
    asm volatile(
        "mma.sync.aligned.m16n8k16.row.col.f32.bf16.bf16.f32 "
        "{%0,%1,%2,%3}, {%4,%5,%6,%7}, {%8,%9}, {%0,%1,%2,%3};"
        : "+f"(d[0]), "+f"(d[1]), "+f"(d[2]), "+f"(d[3])
        : "r"(a[0]), "r"(a[1]), "r"(a[2]), "r"(a[3]), "r"(b0), "r"(b1));
}
__device__ __forceinline__ void ldsm4(uint32_t* r, uint32_t addr) {
    asm volatile("ldmatrix.sync.aligned.m8n8.x4.shared.b16 {%0,%1,%2,%3}, [%4];"
        : "=r"(r[0]), "=r"(r[1]), "=r"(r[2]), "=r"(r[3]) : "r"(addr));
}
__device__ __forceinline__ void split2(float v, __nv_bfloat16& h, __nv_bfloat16& l) {
    h = __float2bfloat16(v);
    l = __float2bfloat16(v - __bfloat162float(h));
}

// bf16x3 compute on one smem stage via ldmatrix (mapping validated in R6).
// KHN = number of k16 halves in the chunk (2 for BK=32, 4 for BK=64).
template<int KHN>
__device__ __forceinline__ void compute_stage_lm(
    uint32_t sAh, uint32_t sAl, uint32_t sBh, uint32_t sBl,
    uint32_t a_off, uint32_t b_off0, uint32_t b_off1, float (*d)[4])
{
    #pragma unroll
    for (int kh = 0; kh < KHN; kh++) {
        const uint32_t ko = kh * 32;   // 16 elems = 32 bytes
        uint32_t ah[4], al[4], bh[4], bl[4];
        ldsm4(ah, sAh + a_off + ko);
        ldsm4(al, sAl + a_off + ko);
        ldsm4(bh, sBh + b_off0 + ko);
        ldsm4(bl, sBl + b_off0 + ko);
        mma_bf16(d[0], ah, bh[0], bh[1]);
        mma_bf16(d[0], ah, bl[0], bl[1]);
        mma_bf16(d[0], al, bh[0], bh[1]);
        mma_bf16(d[1], ah, bh[2], bh[3]);
        mma_bf16(d[1], ah, bl[2], bl[3]);
        mma_bf16(d[1], al, bh[2], bh[3]);
        ldsm4(bh, sBh + b_off1 + ko);
        ldsm4(bl, sBl + b_off1 + ko);
        mma_bf16(d[2], ah, bh[0], bh[1]);
        mma_bf16(d[2], ah, bl[0], bl[1]);
        mma_bf16(d[2], al, bh[0], bh[1]);
        mma_bf16(d[3], ah, bh[2], bh[3]);
        mma_bf16(d[3], ah, bl[2], bl[3]);
        mma_bf16(d[3], al, bh[2], bh[3]);
    }
}
__device__ __forceinline__ uint32_t a_lane_off(int mrow, int lane, int stride) {
    return (uint32_t)(((mrow + (lane & 15)) * stride + ((lane >> 4) & 1) * 8) * 2);
}
__device__ __forceinline__ uint32_t b_lane_off(int ncol, int jp, int lane, int stride) {
    return (uint32_t)(((ncol + jp * 16 + ((lane >> 4) & 1) * 8 + (lane & 7)) * stride
                       + ((lane >> 3) & 1) * 8) * 2);
}

// ---------------------------------------------------------------------------
// Prologue kernels
// ---------------------------------------------------------------------------
__global__ void decomp_kernel(const float* __restrict__ src,
                              __nv_bfloat16* __restrict__ hi,
                              __nv_bfloat16* __restrict__ lo, size_t n4) {
    for (size_t i = (size_t)blockIdx.x * blockDim.x + threadIdx.x; i < n4;
         i += (size_t)gridDim.x * blockDim.x) {
        float4 v = ((const float4*)src)[i];
        __nv_bfloat16 h0, l0, h1, l1, h2, l2, h3, l3;
        split2(v.x, h0, l0); split2(v.y, h1, l1);
        split2(v.z, h2, l2); split2(v.w, h3, l3);
        ((__nv_bfloat162*)hi)[i * 2 + 0] = __halves2bfloat162(h0, h1);
        ((__nv_bfloat162*)hi)[i * 2 + 1] = __halves2bfloat162(h2, h3);
        ((__nv_bfloat162*)lo)[i * 2 + 0] = __halves2bfloat162(l0, l1);
        ((__nv_bfloat162*)lo)[i * 2 + 1] = __halves2bfloat162(l2, l3);
    }
}

__global__ void transpose_decomp_kernel(const float* __restrict__ src, int R, int C,
                                        __nv_bfloat16* __restrict__ dhi,
                                        __nv_bfloat16* __restrict__ dlo) {
    __shared__ float tile[32][33];
    const int bx = blockIdx.x * 32;
    const int by = blockIdx.y * 32;
    const int tx = threadIdx.x, ty = threadIdx.y;
    #pragma unroll
    for (int j = 0; j < 32; j += 8)
        tile[ty + j][tx] = src[(size_t)(by + ty + j) * C + bx + tx];
    __syncthreads();
    #pragma unroll
    for (int j = 0; j < 32; j += 8) {
        float v = tile[tx][ty + j];
        size_t o = (size_t)(bx + ty + j) * R + by + tx;
        __nv_bfloat16 h, l; split2(v, h, l);
        dhi[o] = h; dlo[o] = l;
    }
}

// ---------------------------------------------------------------------------
// xin GEMM: g_xin[t][b][:] = x @ Win  (unchanged from R6)
// ---------------------------------------------------------------------------
__global__ void __launch_bounds__(256) xin_gemm_kernel() {
    extern __shared__ __nv_bfloat16 sm[];
    const uint32_t sbase = s2u(sm);
    const uint32_t pAh = sbase;
    const uint32_t pAl = sbase + 1 * ABYTESX;
    const uint32_t pBh = sbase + 2 * ABYTESX;
    const uint32_t pBl = sbase + 3 * ABYTESX;

    const int tid = threadIdx.x;
    const int wid = tid >> 5, lane = tid & 31;
    const int mrow = (wid & 3) * 16;
    const int ncol = (wid >> 2) * 32;
    const int rowBase = blockIdx.y * BM;
    const int colBase = blockIdx.x * BN;
    const int lr = tid >> 2, lc = (tid & 3) * 8;
    constexpr int NK = I_ / BKX;   // 32

    const uint32_t a_off  = a_lane_off(mrow, lane, STRX);
    const uint32_t b_off0 = b_lane_off(ncol, 0, lane, STRX);
    const uint32_t b_off1 = b_lane_off(ncol, 1, lane, STRX);

    auto issue = [&](int slot, int kc) {
        const int k0 = kc * BKX;
        const size_t ga = (size_t)(rowBase + lr) * I_ + k0 + lc;
        const size_t gb = (size_t)(colBase + lr) * I_ + k0 + lc;
        const uint32_t so = (uint32_t)(slot * SLOTX + lr * STRX + lc) * 2;
        cp16(pAh + so, g_xhi + ga);
        cp16(pAl + so, g_xlo + ga);
        cp16(pBh + so, g_WinT_hi + gb);
        cp16(pBl + so, g_WinT_lo + gb);
        CP_COMMIT();
    };

    issue(0, 0); issue(1, 1); issue(2, 2);
    float d[4][4] = {};

    #pragma unroll 1
    for (int kc = 0; kc < NK; kc++) {
        CP_WAIT(2);
        __syncthreads();
        if (kc + 3 < NK) issue((kc + 3) & 3, kc + 3);
        const uint32_t so = (uint32_t)((kc & 3) * SLOTX) * 2;
        compute_stage_lm<2>(pAh + so, pAl + so, pBh + so, pBl + so,
                            a_off, b_off0, b_off1, d);
    }
    CP_WAIT(0);

    const int g = lane >> 2, tg = lane & 3;
    const int r0 = rowBase + mrow + g;
    const int r1 = r0 + 8;
    const int bb0 = r0 / T_, tt0 = r0 - bb0 * T_;
    const int bb1 = r1 / T_, tt1 = r1 - bb1 * T_;
    #pragma unroll
    for (int j = 0; j < 4; j++) {
        const int col = colBase + ncol + j * 8 + 2 * tg;
        *(float2*)&g_xin[((size_t)tt0 * B_ + bb0) * H_ + col] = make_float2(d[j][0], d[j][1]);
        *(float2*)&g_xin[((size_t)tt1 * B_ + bb1) * H_ + col] = make_float2(d[j][2], d[j][3]);
    }
}

// ---------------------------------------------------------------------------
// Split grid barrier
// ---------------------------------------------------------------------------
__device__ __forceinline__ void bar_arrive(unsigned target) {
    __threadfence();          // h stores visible before arriving
    __syncthreads();          // all threads' stores issued
    if (threadIdx.x == 0) {
        unsigned a = atomicAdd(&g_bar_count, 1);
        if (a == NBLK_STEP - 1) {
            atomicExch(&g_bar_count, 0);
            __threadfence();
            atomicExch(&g_bar_sense, target);
        }
    }
}
__device__ __forceinline__ void bar_wait(unsigned target) {
    if (threadIdx.x == 0) {
        while (atomicAdd(&g_bar_sense, 0) < target) { __nanosleep(64); }
    }
    __syncthreads();
}

// ---------------------------------------------------------------------------
// Persistent recurrence: BK=64, cross-step W prefetch, early arrive.
//
// cp.async group FIFO per step (verified wait discipline):
//   [W'0 W'1 W'2]  (issued during previous step's tail)
//   barrier wait
//   [A0 A1 A2]
//   kc loop: CP_WAIT(2)  ->  at kc=0 drains W'0 W'1 W'2 A0; at kc=1 drains A1;
//            at kc=2 drains A2; at kc>=3 drains WA_kc.  Issue WA_{kc+3} while
//            kc+3 < NK, else W'_{kc+3-NK} (next step's W, slots 0..2 whose
//            previous contents, chunks kc-1, are already consumed).
// ---------------------------------------------------------------------------
__global__ void __launch_bounds__(256) step_persistent_kernel() {
    extern __shared__ __nv_bfloat16 sm[];
    const uint32_t sbase = s2u(sm);
    const uint32_t pAh = sbase;
    const uint32_t pAl = sbase + 1 * ABYTESS;
    const uint32_t pBh = sbase + 2 * ABYTESS;
    const uint32_t pBl = sbase + 3 * ABYTESS;

    const int tid = threadIdx.x;
    const int wid = tid >> 5, lane = tid & 31;
    const int mrow = (wid & 3) * 16;
    const int ncol = (wid >> 2) * 32;
    const int bid = blockIdx.x;
    const int rowBase = (bid >> 5) * BM;   // 4 row tiles
    const int colBase = (bid & 31) * BN;   // 32 col tiles
    // loader: 2 x 16B per array per thread; rows lr, lr+32
    const int lr = tid >> 3;               // 0..31
    const int lc = (tid & 7) * 8;          // 0..56
    constexpr int NK = H_ / BKS;   // 32

    const uint32_t a_off  = a_lane_off(mrow, lane, STRS);
    const uint32_t b_off0 = b_lane_off(ncol, 0, lane, STRS);
    const uint32_t b_off1 = b_lane_off(ncol, 1, lane, STRS);

    __shared__ unsigned s_base;
    if (tid == 0) s_base = atomicAdd(&g_bar_sense, 0u);
    __syncthreads();
    const unsigned base = s_base;

    auto issueW = [&](int slot, int kc) {
        const int k0 = kc * BKS;
        #pragma unroll
        for (int i = 0; i < 2; i++) {
            const size_t gb = (size_t)(colBase + lr + i * 32) * H_ + k0 + lc;
            const uint32_t so = (uint32_t)(slot * SLOTS + (lr + i * 32) * STRS + lc) * 2;
            cp16(pBh + so, g_WT_hi + gb);
            cp16(pBl + so, g_WT_lo + gb);
        }
        CP_COMMIT();
    };

    // prime W for step 0, chunks 0..2
    issueW(0, 0); issueW(1, 1); issueW(2, 2);

    #pragma unroll 1
    for (int t = 0; t < T_; t++) {
        const __nv_bfloat16* ah  = (t & 1) ? g_hB_hi : g_hA_hi;
        const __nv_bfloat16* al  = (t & 1) ? g_hB_lo : g_hA_lo;
        __nv_bfloat16* whi = (t & 1) ? g_hA_hi : g_hB_hi;
        __nv_bfloat16* wlo = (t & 1) ? g_hA_lo : g_hB_lo;

        auto issueA = [&](int slot, int kc) {
            const int k0 = kc * BKS;
            #pragma unroll
            for (int i = 0; i < 2; i++) {
                const size_t ga = (size_t)(rowBase + lr + i * 32) * H_ + k0 + lc;
                const uint32_t so = (uint32_t)(slot * SLOTS + (lr + i * 32) * STRS + lc) * 2;
                cp16(pAh + so, ah + ga);
                cp16(pAl + so, al + ga);
            }
            CP_COMMIT();
        };
        auto issueWA = [&](int slot, int kc) {
            const int k0 = kc * BKS;
            #pragma unroll
            for (int i = 0; i < 2; i++) {
                const size_t ga = (size_t)(rowBase + lr + i * 32) * H_ + k0 + lc;
                const size_t gb = (size_t)(colBase + lr + i * 32) * H_ + k0 + lc;
                const uint32_t so = (uint32_t)(slot * SLOTS + (lr + i * 32) * STRS + lc) * 2;
                cp16(pAh + so, ah + ga);
                cp16(pAl + so, al + ga);
                cp16(pBh + so, g_WT_hi + gb);
                cp16(pBl + so, g_WT_lo + gb);
            }
            CP_COMMIT();
        };

        // h_{t-1} must be ready before issuing A
        if (t > 0) bar_wait(base + (unsigned)t);
        issueA(0, 0); issueA(1, 1); issueA(2, 2);

        float d[4][4] = {};

        #pragma unroll 1
        for (int kc = 0; kc < NK; kc++) {
            CP_WAIT(2);
            __syncthreads();
            if (kc + 3 < NK) issueWA((kc + 3) & 3, kc + 3);
            else             issueW((kc + 3 - NK) & 3, kc + 3 - NK);  // next step W
            const uint32_t so = (uint32_t)((kc & 3) * SLOTS) * 2;
            compute_stage_lm<4>(pAh + so, pAl + so, pBh + so, pBl + so,
                                a_off, b_off0, b_off1, d);
        }

        // Epilogue: h = tanh(xin + acc).  Split stores first, arrive, then
        // fp32 g_hall stores overlap the (next iteration's) barrier wait.
        const int g = lane >> 2, tg = lane & 3;
        const int r0 = rowBase + mrow + g;
        const int r1 = r0 + 8;
        float hv[4][4];
        #pragma unroll
        for (int j = 0; j < 4; j++) {
            const int col = colBase + ncol + j * 8 + 2 * tg;
            const size_t o0 = ((size_t)t * B_ + r0) * H_ + col;
            const size_t o1 = ((size_t)t * B_ + r1) * H_ + col;
            float2 x0 = *(const float2*)&g_xin[o0];
            float2 x1 = *(const float2*)&g_xin[o1];
            hv[j][0] = tanhf(x0.x + d[j][0]);
            hv[j][1] = tanhf(x0.y + d[j][1]);
            hv[j][2] = tanhf(x1.x + d[j][2]);
            hv[j][3] = tanhf(x1.y + d[j][3]);
            __nv_bfloat16 e0, f0, e1, f1, e2, f2, e3, f3;
            split2(hv[j][0], e0, f0); split2(hv[j][1], e1, f1);
            split2(hv[j][2], e2, f2); split2(hv[j][3], e3, f3);
            const size_t w0 = (size_t)r0 * H_ + col;
            const size_t w1 = (size_t)r1 * H_ + col;
            *(__nv_bfloat162*)&whi[w0] = __halves2bfloat162(e0, e1);
            *(__nv_bfloat162*)&wlo[w0] = __halves2bfloat162(f0, f1);
            *(__nv_bfloat162*)&whi[w1] = __halves2bfloat162(e2, e3);
            *(__nv_bfloat162*)&wlo[w1] = __halves2bfloat162(f2, f3);
        }

        if (t < T_ - 1) bar_arrive(base + (unsigned)t + 1u);

        // fp32 history stores (only out_kernel reads these) — overlap barrier
        #pragma unroll
        for (int j = 0; j < 4; j++) {
            const int col = colBase + ncol + j * 8 + 2 * tg;
            const size_t o0 = ((size_t)t * B_ + r0) * H_ + col;
            const size_t o1 = ((size_t)t * B_ + r1) * H_ + col;
            *(float2*)&g_hall[o0] = make_float2(hv[j][0], hv[j][1]);
            *(float2*)&g_hall[o1] = make_float2(hv[j][2], hv[j][3]);
        }
    }
    CP_WAIT(0);   // drain trailing W prefetch before exit
}

// ---------------------------------------------------------------------------
// Output head
// ---------------------------------------------------------------------------
__global__ void __launch_bounds__(256) out_kernel(
    const float* __restrict__ lin_w,
    const float* __restrict__ lin_b,
    float* __restrict__ out)
{
    const int bt = blockIdx.x;
    const int t = bt / B_;
    const int b = bt % B_;
    const int tid = threadIdx.x;

    const float* hrow = g_hall + ((size_t)t * B_ + b) * H_;

    float hreg[H_ / 256];
    #pragma unroll
    for (int i = 0; i < H_ / 256; i++)
        hreg[i] = hrow[i * 256 + tid];

    float acc[O_];
    #pragma unroll
    for (int o = 0; o < O_; o++) {
        float s = 0.f;
        #pragma unroll
        for (int i = 0; i < H_ / 256; i++)
            s += hreg[i] * lin_w[(size_t)o * H_ + i * 256 + tid];
        acc[o] = s;
    }

    #pragma unroll
    for (int off = 16; off > 0; off >>= 1)
        #pragma unroll
        for (int o = 0; o < O_; o++)
            acc[o] += __shfl_xor_sync(0xFFFFFFFFu, acc[o], off);

    __shared__ float wsum[8][O_];
    const int lane = tid & 31;
    const int w = tid >> 5;
    if (lane == 0)
        #pragma unroll
        for (int o = 0; o < O_; o++)
            wsum[w][o] = acc[o];
    __syncthreads();

    if (tid < O_) {
        float s = lin_b[tid];
        #pragma unroll
        for (int ww = 0; ww < 8; ww++)
            s += wsum[ww][tid];
        out[((size_t)b * T_ + t) * O_ + tid] = s;
    }
}

// ---------------------------------------------------------------------------
extern "C" void kernel_launch(void* const* d_in, const int* in_sizes, int n_in,
                              void* d_out, int out_size)
{
    const float* x     = (const float*)d_in[0];
    const float* h0    = (const float*)d_in[1];
    const float* Win   = (const float*)d_in[2];
    const float* W     = (const float*)d_in[3];
    const float* lin_w = (const float*)d_in[4];
    const float* lin_b = (const float*)d_in[5];
    float* out = (float*)d_out;

    __nv_bfloat16 *xhi, *xlo, *winT_hi, *winT_lo, *wT_hi, *wT_lo, *hA_hi, *hA_lo;
    cudaGetSymbolAddress((void**)&xhi, g_xhi);
    cudaGetSymbolAddress((void**)&xlo, g_xlo);
    cudaGetSymbolAddress((void**)&winT_hi, g_WinT_hi);
    cudaGetSymbolAddress((void**)&winT_lo, g_WinT_lo);
    cudaGetSymbolAddress((void**)&wT_hi, g_WT_hi);
    cudaGetSymbolAddress((void**)&wT_lo, g_WT_lo);
    cudaGetSymbolAddress((void**)&hA_hi, g_hA_hi);
    cudaGetSymbolAddress((void**)&hA_lo, g_hA_lo);

    static bool attr_done = false;
    if (!attr_done) {
        cudaFuncSetAttribute(xin_gemm_kernel,
                             cudaFuncAttributeMaxDynamicSharedMemorySize, SMEM_X);
        cudaFuncSetAttribute(step_persistent_kernel,
                             cudaFuncAttributeMaxDynamicSharedMemorySize, SMEM_S);
        attr_done = true;
    }

    // Prologue
    decomp_kernel<<<4096, 256>>>(x, xhi, xlo, (size_t)M1 * I_ / 4);
    decomp_kernel<<<512, 256>>>(h0, hA_hi, hA_lo, (size_t)B_ * H_ / 4);
    transpose_decomp_kernel<<<dim3(H_ / 32, I_ / 32), dim3(32, 8)>>>(Win, I_, H_, winT_hi, winT_lo);
    transpose_decomp_kernel<<<dim3(H_ / 32, H_ / 32), dim3(32, 8)>>>(W, H_, H_, wT_hi, wT_lo);

    // Input projection
    xin_gemm_kernel<<<dim3(H_ / BN, M1 / BM), 256, SMEM_X>>>();

    // Full recurrence
    step_persistent_kernel<<<NBLK_STEP, 256, SMEM_S>>>();

    // Output head
    out_kernel<<<T_ * B_, 256>>>(lin_w, lin_b, out);
}

// round 9
// speedup vs baseline: 1.3039x; 1.0771x over previous
#include <cuda_runtime.h>
#include <cuda_bf16.h>
#include <cstdint>
#include <cstddef>

// ---------------------------------------------------------------------------
// Problem constants
// ---------------------------------------------------------------------------
#define B_  256
#define T_  100
#define I_  1024
#define H_  2048
#define O_  10
#define M1  (B_ * T_)   // 25600

// Common tile: 64x64 CTA, 8 warps (4m x 2n), warp 16x32; BK=64
#define BM 64
#define BN 64
#define BKS 64
#define STRS 72                        // 144B rows; conflict-free ldmatrix
#define SLOTS (BM * STRS)              // 4608 elems per array per stage

// step kernel: 4 stages
#define NSTG_S 4
#define ABYTESS (NSTG_S * SLOTS * 2)   // 36864 B per operand array
#define SMEM_S  (4 * ABYTESS)          // 147456 B
#define NBLK_STEP 128
#define NROWG 4                        // barrier groups (one per rowBase)
#define GRP_CTAS 32

// xin kernel: 3 stages (2 CTAs/SM)
#define NSTG_X 3
#define ABYTESX (NSTG_X * SLOTS * 2)   // 27648 B per operand array
#define SMEM_X  (4 * ABYTESX)          // 110592 B

// ---------------------------------------------------------------------------
// Device scratch
// ---------------------------------------------------------------------------
__device__ float g_xin [(size_t)T_ * B_ * H_];           // [t][b][h]
__device__ __nv_bfloat16 g_hh_hi[(size_t)T_ * B_ * H_];  // h history hi
__device__ __nv_bfloat16 g_hh_lo[(size_t)T_ * B_ * H_];  // h history lo
__device__ __nv_bfloat16 g_xhi[(size_t)M1 * I_];
__device__ __nv_bfloat16 g_xlo[(size_t)M1 * I_];
__device__ __nv_bfloat16 g_WinT_hi[(size_t)H_ * I_];     // [h][i]
__device__ __nv_bfloat16 g_WinT_lo[(size_t)H_ * I_];
__device__ __nv_bfloat16 g_WT_hi[(size_t)H_ * H_];       // [n][k]
__device__ __nv_bfloat16 g_WT_lo[(size_t)H_ * H_];
__device__ __nv_bfloat16 g_hA_hi[(size_t)B_ * H_], g_hA_lo[(size_t)B_ * H_];  // h0 split
__device__ unsigned g_bar_count4[NROWG] = {0, 0, 0, 0};
__device__ unsigned g_bar_sense4[NROWG] = {0, 0, 0, 0};

// ---------------------------------------------------------------------------
// Helpers
// ---------------------------------------------------------------------------
__device__ __forceinline__ uint32_t s2u(const void* p) {
    uint32_t a;
    asm("{ .reg .u64 t; cvta.to.shared.u64 t, %1; cvt.u32.u64 %0, t; }" : "=r"(a) : "l"(p));
    return a;
}
__device__ __forceinline__ void cp16(uint32_t s, const void* g) {
    asm volatile("cp.async.cg.shared.global [%0], [%1], 16;" :: "r"(s), "l"(g));
}
#define CP_COMMIT()  asm volatile("cp.async.commit_group;")
#define CP_WAIT(N)   asm volatile("cp.async.wait_group %0;" :: "n"(N))

__device__ __forceinline__ void mma_bf16(float* d, const uint32_t* a, uint32_t b0, uint32_t b1) {
    asm volatile(
        "mma.sync.aligned.m16n8k16.row.col.f32.bf16.bf16.f32 "
        "{%0,%1,%2,%3}, {%4,%5,%6,%7}, {%8,%9}, {%0,%1,%2,%3};"
        : "+f"(d[0]), "+f"(d[1]), "+f"(d[2]), "+f"(d[3])
        : "r"(a[0]), "r"(a[1]), "r"(a[2]), "r"(a[3]), "r"(b0), "r"(b1));
}
__device__ __forceinline__ void ldsm4(uint32_t* r, uint32_t addr) {
    asm volatile("ldmatrix.sync.aligned.m8n8.x4.shared.b16 {%0,%1,%2,%3}, [%4];"
        : "=r"(r[0]), "=r"(r[1]), "=r"(r[2]), "=r"(r[3]) : "r"(addr));
}
__device__ __forceinline__ void split2(float v, __nv_bfloat16& h, __nv_bfloat16& l) {
    h = __float2bfloat16(v);
    l = __float2bfloat16(v - __bfloat162float(h));
}

// bf16x3 compute on one smem stage via ldmatrix (mapping validated in R6).
__device__ __forceinline__ void compute_stage_lm(
    uint32_t sAh, uint32_t sAl, uint32_t sBh, uint32_t sBl,
    uint32_t a_off, uint32_t b_off0, uint32_t b_off1, float (*d)[4])
{
    #pragma unroll
    for (int kh = 0; kh < 4; kh++) {       // BK=64 -> 4 k16 halves
        const uint32_t ko = kh * 32;
        uint32_t ah[4], al[4], bh[4], bl[4];
        ldsm4(ah, sAh + a_off + ko);
        ldsm4(al, sAl + a_off + ko);
        ldsm4(bh, sBh + b_off0 + ko);
        ldsm4(bl, sBl + b_off0 + ko);
        mma_bf16(d[0], ah, bh[0], bh[1]);
        mma_bf16(d[0], ah, bl[0], bl[1]);
        mma_bf16(d[0], al, bh[0], bh[1]);
        mma_bf16(d[1], ah, bh[2], bh[3]);
        mma_bf16(d[1], ah, bl[2], bl[3]);
        mma_bf16(d[1], al, bh[2], bh[3]);
        ldsm4(bh, sBh + b_off1 + ko);
        ldsm4(bl, sBl + b_off1 + ko);
        mma_bf16(d[2], ah, bh[0], bh[1]);
        mma_bf16(d[2], ah, bl[0], bl[1]);
        mma_bf16(d[2], al, bh[0], bh[1]);
        mma_bf16(d[3], ah, bh[2], bh[3]);
        mma_bf16(d[3], ah, bl[2], bl[3]);
        mma_bf16(d[3], al, bh[2], bh[3]);
    }
}
__device__ __forceinline__ uint32_t a_lane_off(int mrow, int lane) {
    return (uint32_t)(((mrow + (lane & 15)) * STRS + ((lane >> 4) & 1) * 8) * 2);
}
__device__ __forceinline__ uint32_t b_lane_off(int ncol, int jp, int lane) {
    return (uint32_t)(((ncol + jp * 16 + ((lane >> 4) & 1) * 8 + (lane & 7)) * STRS
                       + ((lane >> 3) & 1) * 8) * 2);
}

// ---------------------------------------------------------------------------
// Prologue kernels
// ---------------------------------------------------------------------------
__global__ void decomp_kernel(const float* __restrict__ src,
                              __nv_bfloat16* __restrict__ hi,
                              __nv_bfloat16* __restrict__ lo, size_t n4) {
    for (size_t i = (size_t)blockIdx.x * blockDim.x + threadIdx.x; i < n4;
         i += (size_t)gridDim.x * blockDim.x) {
        float4 v = ((const float4*)src)[i];
        __nv_bfloat16 h0, l0, h1, l1, h2, l2, h3, l3;
        split2(v.x, h0, l0); split2(v.y, h1, l1);
        split2(v.z, h2, l2); split2(v.w, h3, l3);
        ((__nv_bfloat162*)hi)[i * 2 + 0] = __halves2bfloat162(h0, h1);
        ((__nv_bfloat162*)hi)[i * 2 + 1] = __halves2bfloat162(h2, h3);
        ((__nv_bfloat162*)lo)[i * 2 + 0] = __halves2bfloat162(l0, l1);
        ((__nv_bfloat162*)lo)[i * 2 + 1] = __halves2bfloat162(l2, l3);
    }
}

__global__ void transpose_decomp_kernel(const float* __restrict__ src, int R, int C,
                                        __nv_bfloat16* __restrict__ dhi,
                                        __nv_bfloat16* __restrict__ dlo) {
    __shared__ float tile[32][33];
    const int bx = blockIdx.x * 32;
    const int by = blockIdx.y * 32;
    const int tx = threadIdx.x, ty = threadIdx.y;
    #pragma unroll
    for (int j = 0; j < 32; j += 8)
        tile[ty + j][tx] = src[(size_t)(by + ty + j) * C + bx + tx];
    __syncthreads();
    #pragma unroll
    for (int j = 0; j < 32; j += 8) {
        float v = tile[tx][ty + j];
        size_t o = (size_t)(bx + ty + j) * R + by + tx;
        __nv_bfloat16 h, l; split2(v, h, l);
        dhi[o] = h; dlo[o] = l;
    }
}

// ---------------------------------------------------------------------------
// xin GEMM: g_xin[t][b][:] = x @ Win.  BK=64, 3-stage, 2 CTAs/SM.
// ---------------------------------------------------------------------------
__global__ void __launch_bounds__(256, 2) xin_gemm_kernel() {
    extern __shared__ __nv_bfloat16 sm[];
    const uint32_t sbase = s2u(sm);
    const uint32_t pAh = sbase;
    const uint32_t pAl = sbase + 1 * ABYTESX;
    const uint32_t pBh = sbase + 2 * ABYTESX;
    const uint32_t pBl = sbase + 3 * ABYTESX;

    const int tid = threadIdx.x;
    const int wid = tid >> 5, lane = tid & 31;
    const int mrow = (wid & 3) * 16;
    const int ncol = (wid >> 2) * 32;
    const int rowBase = blockIdx.y * BM;
    const int colBase = blockIdx.x * BN;
    const int lr = tid >> 3;               // 0..31
    const int lc = (tid & 7) * 8;          // 0..56
    constexpr int NK = I_ / BKS;   // 16

    const uint32_t a_off  = a_lane_off(mrow, lane);
    const uint32_t b_off0 = b_lane_off(ncol, 0, lane);
    const uint32_t b_off1 = b_lane_off(ncol, 1, lane);

    auto issue = [&](int slot, int kc) {
        const int k0 = kc * BKS;
        #pragma unroll
        for (int i = 0; i < 2; i++) {
            const size_t ga = (size_t)(rowBase + lr + i * 32) * I_ + k0 + lc;
            const size_t gb = (size_t)(colBase + lr + i * 32) * I_ + k0 + lc;
            const uint32_t so = (uint32_t)(slot * SLOTS + (lr + i * 32) * STRS + lc) * 2;
            cp16(pAh + so, g_xhi + ga);
            cp16(pAl + so, g_xlo + ga);
            cp16(pBh + so, g_WinT_hi + gb);
            cp16(pBl + so, g_WinT_lo + gb);
        }
        CP_COMMIT();
    };

    issue(0, 0); issue(1, 1);
    float d[4][4] = {};

    int slot = 0;
    #pragma unroll 1
    for (int kc = 0; kc < NK; kc++) {
        CP_WAIT(1);
        __syncthreads();
        if (kc + 2 < NK) {
            int s2 = slot + 2; if (s2 >= NSTG_X) s2 -= NSTG_X;
            issue(s2, kc + 2);
        }
        const uint32_t so = (uint32_t)(slot * SLOTS) * 2;
        compute_stage_lm(pAh + so, pAl + so, pBh + so, pBl + so,
                         a_off, b_off0, b_off1, d);
        if (++slot == NSTG_X) slot = 0;
    }
    CP_WAIT(0);

    const int g = lane >> 2, tg = lane & 3;
    const int r0 = rowBase + mrow + g;
    const int r1 = r0 + 8;
    const int bb0 = r0 / T_, tt0 = r0 - bb0 * T_;
    const int bb1 = r1 / T_, tt1 = r1 - bb1 * T_;
    #pragma unroll
    for (int j = 0; j < 4; j++) {
        const int col = colBase + ncol + j * 8 + 2 * tg;
        *(float2*)&g_xin[((size_t)tt0 * B_ + bb0) * H_ + col] = make_float2(d[j][0], d[j][1]);
        *(float2*)&g_xin[((size_t)tt1 * B_ + bb1) * H_ + col] = make_float2(d[j][2], d[j][3]);
    }
}

// ---------------------------------------------------------------------------
// Per-rowgroup split grid barrier (32 arrivals each)
// ---------------------------------------------------------------------------
__device__ __forceinline__ void bar_arrive(int grp, unsigned target) {
    __threadfence();
    __syncthreads();
    if (threadIdx.x == 0) {
        unsigned a = atomicAdd(&g_bar_count4[grp], 1);
        if (a == GRP_CTAS - 1) {
            atomicExch(&g_bar_count4[grp], 0);
            __threadfence();
            atomicExch(&g_bar_sense4[grp], target);
        }
    }
}
__device__ __forceinline__ void bar_wait(int grp, unsigned target) {
    if (threadIdx.x == 0) {
        while (atomicAdd(&g_bar_sense4[grp], 0) < target) { __nanosleep(64); }
    }
    __syncthreads();
}

// ---------------------------------------------------------------------------
// Persistent recurrence: BK=64, 4-stage, cross-step W prefetch,
// per-rowgroup barriers, bf16 hi/lo history epilogue.
// ---------------------------------------------------------------------------
__global__ void __launch_bounds__(256) step_persistent_kernel() {
    extern __shared__ __nv_bfloat16 sm[];
    const uint32_t sbase = s2u(sm);
    const uint32_t pAh = sbase;
    const uint32_t pAl = sbase + 1 * ABYTESS;
    const uint32_t pBh = sbase + 2 * ABYTESS;
    const uint32_t pBl = sbase + 3 * ABYTESS;

    const int tid = threadIdx.x;
    const int wid = tid >> 5, lane = tid & 31;
    const int mrow = (wid & 3) * 16;
    const int ncol = (wid >> 2) * 32;
    const int bid = blockIdx.x;
    const int grp = bid >> 5;              // rowgroup 0..3
    const int rowBase = grp * BM;
    const int colBase = (bid & 31) * BN;
    const int lr = tid >> 3;               // 0..31
    const int lc = (tid & 7) * 8;          // 0..56
    constexpr int NK = H_ / BKS;   // 32

    const uint32_t a_off  = a_lane_off(mrow, lane);
    const uint32_t b_off0 = b_lane_off(ncol, 0, lane);
    const uint32_t b_off1 = b_lane_off(ncol, 1, lane);

    __shared__ unsigned s_base;
    if (tid == 0) s_base = atomicAdd(&g_bar_sense4[grp], 0u);
    __syncthreads();
    const unsigned base = s_base;

    auto issueW = [&](int slot, int kc) {
        const int k0 = kc * BKS;
        #pragma unroll
        for (int i = 0; i < 2; i++) {
            const size_t gb = (size_t)(colBase + lr + i * 32) * H_ + k0 + lc;
            const uint32_t so = (uint32_t)(slot * SLOTS + (lr + i * 32) * STRS + lc) * 2;
            cp16(pBh + so, g_WT_hi + gb);
            cp16(pBl + so, g_WT_lo + gb);
        }
        CP_COMMIT();
    };

    issueW(0, 0); issueW(1, 1); issueW(2, 2);

    #pragma unroll 1
    for (int t = 0; t < T_; t++) {
        const __nv_bfloat16* ah = (t == 0) ? g_hA_hi : (g_hh_hi + (size_t)(t - 1) * B_ * H_);
        const __nv_bfloat16* al = (t == 0) ? g_hA_lo : (g_hh_lo + (size_t)(t - 1) * B_ * H_);
        __nv_bfloat16* whi = g_hh_hi + (size_t)t * B_ * H_;
        __nv_bfloat16* wlo = g_hh_lo + (size_t)t * B_ * H_;

        auto issueA = [&](int slot, int kc) {
            const int k0 = kc * BKS;
            #pragma unroll
            for (int i = 0; i < 2; i++) {
                const size_t ga = (size_t)(rowBase + lr + i * 32) * H_ + k0 + lc;
                const uint32_t so = (uint32_t)(slot * SLOTS + (lr + i * 32) * STRS + lc) * 2;
                cp16(pAh + so, ah + ga);
                cp16(pAl + so, al + ga);
            }
            CP_COMMIT();
        };
        auto issueWA = [&](int slot, int kc) {
            const int k0 = kc * BKS;
            #pragma unroll
            for (int i = 0; i < 2; i++) {
                const size_t ga = (size_t)(rowBase + lr + i * 32) * H_ + k0 + lc;
                const size_t gb = (size_t)(colBase + lr + i * 32) * H_ + k0 + lc;
                const uint32_t so = (uint32_t)(slot * SLOTS + (lr + i * 32) * STRS + lc) * 2;
                cp16(pAh + so, ah + ga);
                cp16(pAl + so, al + ga);
                cp16(pBh + so, g_WT_hi + gb);
                cp16(pBl + so, g_WT_lo + gb);
            }
            CP_COMMIT();
        };

        if (t > 0) bar_wait(grp, base + (unsigned)t);
        issueA(0, 0); issueA(1, 1); issueA(2, 2);

        float d[4][4] = {};

        #pragma unroll 1
        for (int kc = 0; kc < NK; kc++) {
            CP_WAIT(2);
            __syncthreads();
            if (kc + 3 < NK) issueWA((kc + 3) & 3, kc + 3);
            else             issueW((kc + 3 - NK) & 3, kc + 3 - NK);
            const uint32_t so = (uint32_t)((kc & 3) * SLOTS) * 2;
            compute_stage_lm(pAh + so, pAl + so, pBh + so, pBl + so,
                             a_off, b_off0, b_off1, d);
        }

        // Epilogue: h = tanh(xin + acc) -> bf16 hi/lo history only
        const int g = lane >> 2, tg = lane & 3;
        const int r0 = rowBase + mrow + g;
        const int r1 = r0 + 8;
        #pragma unroll
        for (int j = 0; j < 4; j++) {
            const int col = colBase + ncol + j * 8 + 2 * tg;
            const size_t o0 = ((size_t)t * B_ + r0) * H_ + col;
            const size_t o1 = ((size_t)t * B_ + r1) * H_ + col;
            float2 x0 = *(const float2*)&g_xin[o0];
            float2 x1 = *(const float2*)&g_xin[o1];
            float h00 = tanhf(x0.x + d[j][0]);
            float h01 = tanhf(x0.y + d[j][1]);
            float h10 = tanhf(x1.x + d[j][2]);
            float h11 = tanhf(x1.y + d[j][3]);
            __nv_bfloat16 e0, f0, e1, f1, e2, f2, e3, f3;
            split2(h00, e0, f0); split2(h01, e1, f1);
            split2(h10, e2, f2); split2(h11, e3, f3);
            const size_t w0 = (size_t)r0 * H_ + col;
            const size_t w1 = (size_t)r1 * H_ + col;
            *(__nv_bfloat162*)&whi[w0] = __halves2bfloat162(e0, e1);
            *(__nv_bfloat162*)&wlo[w0] = __halves2bfloat162(f0, f1);
            *(__nv_bfloat162*)&whi[w1] = __halves2bfloat162(e2, e3);
            *(__nv_bfloat162*)&wlo[w1] = __halves2bfloat162(f2, f3);
        }

        if (t < T_ - 1) bar_arrive(grp, base + (unsigned)t + 1u);
    }
    CP_WAIT(0);
}

// ---------------------------------------------------------------------------
// Output head: h reconstructed from bf16 hi+lo history
// ---------------------------------------------------------------------------
__global__ void __launch_bounds__(256) out_kernel(
    const float* __restrict__ lin_w,
    const float* __restrict__ lin_b,
    float* __restrict__ out)
{
    const int bt = blockIdx.x;
    const int t = bt / B_;
    const int b = bt % B_;
    const int tid = threadIdx.x;

    const __nv_bfloat16* hhi = g_hh_hi + ((size_t)t * B_ + b) * H_;
    const __nv_bfloat16* hlo = g_hh_lo + ((size_t)t * B_ + b) * H_;

    float hreg[H_ / 256];
    #pragma unroll
    for (int i = 0; i < H_ / 256; i++)
        hreg[i] = __bfloat162float(hhi[i * 256 + tid]) + __bfloat162float(hlo[i * 256 + tid]);

    float acc[O_];
    #pragma unroll
    for (int o = 0; o < O_; o++) {
        float s = 0.f;
        #pragma unroll
        for (int i = 0; i < H_ / 256; i++)
            s += hreg[i] * lin_w[(size_t)o * H_ + i * 256 + tid];
        acc[o] = s;
    }

    #pragma unroll
    for (int off = 16; off > 0; off >>= 1)
        #pragma unroll
        for (int o = 0; o < O_; o++)
            acc[o] += __shfl_xor_sync(0xFFFFFFFFu, acc[o], off);

    __shared__ float wsum[8][O_];
    const int lane = tid & 31;
    const int w = tid >> 5;
    if (lane == 0)
        #pragma unroll
        for (int o = 0; o < O_; o++)
            wsum[w][o] = acc[o];
    __syncthreads();

    if (tid < O_) {
        float s = lin_b[tid];
        #pragma unroll
        for (int ww = 0; ww < 8; ww++)
            s += wsum[ww][tid];
        out[((size_t)b * T_ + t) * O_ + tid] = s;
    }
}

// ---------------------------------------------------------------------------
extern "C" void kernel_launch(void* const* d_in, const int* in_sizes, int n_in,
                              void* d_out, int out_size)
{
    const float* x     = (const float*)d_in[0];
    const float* h0    = (const float*)d_in[1];
    const float* Win   = (const float*)d_in[2];
    const float* W     = (const float*)d_in[3];
    const float* lin_w = (const float*)d_in[4];
    const float* lin_b = (const float*)d_in[5];
    float* out = (float*)d_out;

    __nv_bfloat16 *xhi, *xlo, *winT_hi, *winT_lo, *wT_hi, *wT_lo, *hA_hi, *hA_lo;
    cudaGetSymbolAddress((void**)&xhi, g_xhi);
    cudaGetSymbolAddress((void**)&xlo, g_xlo);
    cudaGetSymbolAddress((void**)&winT_hi, g_WinT_hi);
    cudaGetSymbolAddress((void**)&winT_lo, g_WinT_lo);
    cudaGetSymbolAddress((void**)&wT_hi, g_WT_hi);
    cudaGetSymbolAddress((void**)&wT_lo, g_WT_lo);
    cudaGetSymbolAddress((void**)&hA_hi, g_hA_hi);
    cudaGetSymbolAddress((void**)&hA_lo, g_hA_lo);

    static bool attr_done = false;
    if (!attr_done) {
        cudaFuncSetAttribute(xin_gemm_kernel,
                             cudaFuncAttributeMaxDynamicSharedMemorySize, SMEM_X);
        cudaFuncSetAttribute(step_persistent_kernel,
                             cudaFuncAttributeMaxDynamicSharedMemorySize, SMEM_S);
        attr_done = true;
    }

    // Prologue
    decomp_kernel<<<4096, 256>>>(x, xhi, xlo, (size_t)M1 * I_ / 4);
    decomp_kernel<<<512, 256>>>(h0, hA_hi, hA_lo, (size_t)B_ * H_ / 4);
    transpose_decomp_kernel<<<dim3(H_ / 32, I_ / 32), dim3(32, 8)>>>(Win, I_, H_, winT_hi, winT_lo);
    transpose_decomp_kernel<<<dim3(H_ / 32, H_ / 32), dim3(32, 8)>>>(W, H_, H_, wT_hi, wT_lo);

    // Input projection
    xin_gemm_kernel<<<dim3(H_ / BN, M1 / BM), 256, SMEM_X>>>();

    // Full recurrence
    step_persistent_kernel<<<NBLK_STEP, 256, SMEM_S>>>();

    // Output head
    out_kernel<<<T_ * B_, 256>>>(lin_w, lin_b, out);
}